// round 2
// baseline (speedup 1.0000x reference)
#include <cuda_runtime.h>
#include <math.h>

typedef unsigned long long u64;

#define N_SAMP 256
#define T_LEN  36
#define NPOLE  80
#define F_DIM  50
#define K_DIM  161                    // 1 + 2*80
#define NCOLS  (N_SAMP * F_DIM)      // 12800
#define NKF    (N_SAMP * K_DIM * F_DIM)  // 2,060,800
#define LAM    0.1f
#define ITERS  100

#define C_TILE 44          // columns per block-tile
#define PGRP   11          // pair-groups (4 cols each) -> 44 cols
#define RGRP   23          // row groups (7 rows each) -> 161 rows
#define RPT    7
#define NTHREADS 256
#define NACTIVE  253       // 23 * 11
#define NTILES   291       // ceil(12800/44)
#define AROW     184       // padded A row stride in floats (23 groups * 8)
#define SM_A   (K_DIM * AROW)     // 29624 floats
#define SM_Y   (K_DIM * C_TILE)   // 7084 floats
#define SMEM_FISTA ((SM_A + 3 * SM_Y) * 4)   // 203,504 bytes

// ---------------- device scratch (no allocation allowed) ----------------
__device__ float  g_D[T_LEN * K_DIM];
__device__ float  g_A[K_DIM * K_DIM];
__device__ float  g_c0[NKF];
__device__ float  g_x1[NKF];
__device__ float  g_scal[4];   // 0: Linv, 1: lam/L, 2: wscale
__device__ double g_wn2;

// ---------------- f32x2 helpers (Blackwell packed fp32) ----------------
__device__ __forceinline__ u64 dupf(float a) {
    u64 r; asm("mov.b64 %0, {%1, %1};" : "=l"(r) : "f"(a)); return r;
}
__device__ __forceinline__ void fma2(u64 &d, u64 a, u64 b) {
    asm("fma.rn.f32x2 %0, %1, %2, %3;" : "=l"(d) : "l"(a), "l"(b), "l"(d));
}
__device__ __forceinline__ float2 unpk(u64 v) {
    float2 r; asm("mov.b64 {%0, %1}, %2;" : "=f"(r.x), "=f"(r.y) : "l"(v)); return r;
}

// ---------------- setup: build D, DtD, L, A = I - DtD/L ----------------
__global__ void setup_kernel(const float* __restrict__ rr, const float* __restrict__ theta) {
    int tid = threadIdx.x;
    for (int idx = tid; idx < T_LEN * K_DIM; idx += blockDim.x) {
        int t = idx / K_DIM, k = idx - (idx / K_DIM) * K_DIM;
        float v;
        if (k == 0) v = 1.0f;
        else if (k <= NPOLE) {
            int p = k - 1;
            v = powf(rr[p], (float)t) * cosf((float)t * theta[p]);
        } else {
            int p = k - 1 - NPOLE;
            v = powf(rr[p], (float)t) * sinf((float)t * theta[p]);
        }
        g_D[idx] = v;
    }
    if (tid == 0) g_wn2 = 0.0;
    __syncthreads();

    __shared__ double red[256];
    double local = 0.0;
    for (int idx = tid; idx < K_DIM * K_DIM; idx += blockDim.x) {
        int a = idx / K_DIM, b = idx - a * K_DIM;
        float s = 0.f;
        for (int t = 0; t < T_LEN; t++) s = fmaf(g_D[t * K_DIM + a], g_D[t * K_DIM + b], s);
        g_A[idx] = s;                        // temporarily DtD
        local += (double)s * (double)s;
    }
    red[tid] = local;
    __syncthreads();
    for (int o = 128; o > 0; o >>= 1) { if (tid < o) red[tid] += red[tid + o]; __syncthreads(); }
    __shared__ float sLinv;
    if (tid == 0) {
        float L = (float)sqrt(red[0]);       // Frobenius norm of DtD
        g_scal[0] = 1.0f / L;
        g_scal[1] = LAM / L;
        sLinv = 1.0f / L;
    }
    __syncthreads();
    float Linv = sLinv;
    for (int idx = tid; idx < K_DIM * K_DIM; idx += blockDim.x) {
        int a = idx / K_DIM, b = idx - a * K_DIM;
        float v = -g_A[idx] * Linv;
        if (a == b) v += 1.0f;
        g_A[idx] = v;                        // A = I - DtD/L  (symmetric)
    }
}

// ---------------- c0 = (D^T Y) / L ----------------
__global__ void dty_kernel(const float* __restrict__ x) {
    __shared__ float xs[T_LEN * F_DIM];
    __shared__ float Ds[T_LEN * K_DIM];
    int n = blockIdx.x, tid = threadIdx.x;
    for (int i = tid; i < T_LEN * F_DIM; i += blockDim.x) xs[i] = x[n * T_LEN * F_DIM + i];
    for (int i = tid; i < T_LEN * K_DIM; i += blockDim.x) Ds[i] = g_D[i];
    __syncthreads();
    float Linv = g_scal[0];
    for (int o = tid; o < K_DIM * F_DIM; o += blockDim.x) {
        int k = o / F_DIM, f = o - k * F_DIM;
        float s = 0.f;
        for (int t = 0; t < T_LEN; t++) s = fmaf(Ds[t * K_DIM + k], xs[t * F_DIM + f], s);
        g_c0[n * K_DIM * F_DIM + o] = s * Linv;
    }
}

// ---------------- FISTA: 100 iterations, tile fully resident ----------------
template <int PHASE>
__global__ __launch_bounds__(NTHREADS, 1)
void fista_kernel(float* __restrict__ code_out) {
    extern __shared__ float smem[];
    float* sA = smem;            // padded A
    float* sY = sA + SM_A;       // y tile [k][col]
    float* sC = sY + SM_Y;       // c0 tile
    float* sW = sC + SM_Y;       // wl tile (phase 2)

    const int tid = threadIdx.x;
    const bool active = tid < NACTIVE;
    const int p = tid % PGRP;        // pair-group -> cols 4p..4p+3
    const int r = tid / PGRP;        // row-group -> rows 7r..7r+6
    const int k0 = r * RPT;
    const float lamLinv = g_scal[1];
    const float wscale  = g_scal[2];

    // stage A into padded layout: sA[j*184 + (k/7)*8 + k%7] = A[j][k] (symmetric)
    for (int idx = tid; idx < K_DIM * K_DIM; idx += NTHREADS) {
        int j = idx / K_DIM, k = idx - j * K_DIM;
        sA[j * AROW + (k / RPT) * 8 + (k % RPT)] = g_A[idx];
    }

    const int tile = blockIdx.x;
    const int col0 = tile * C_TILE;

    for (int i = tid; i < K_DIM * C_TILE; i += NTHREADS) {
        int k = i / C_TILE, c = i - k * C_TILE;
        int col = col0 + c; if (col >= NCOLS) col = NCOLS - 1;
        int n = col / F_DIM, f = col - n * F_DIM;
        int g = (n * K_DIM + k) * F_DIM + f;
        sC[i] = g_c0[g];
        if (PHASE == 2) sW[i] = wscale / (fabsf(g_x1[g]) + 0.01f);
    }
    for (int i = tid; i < SM_Y; i += NTHREADS) sY[i] = 0.0f;
    __syncthreads();

    float xo[RPT][4];
    #pragma unroll
    for (int i = 0; i < RPT; i++) { xo[i][0] = xo[i][1] = xo[i][2] = xo[i][3] = 0.f; }
    float t_old = 1.0f;

    const float* aBase = sA + (r << 3);
    const float* yBase = sY + (p << 2);

    for (int it = 0; it < ITERS; it++) {
        u64 acc[RPT][2];
        #pragma unroll
        for (int i = 0; i < RPT; i++) { acc[i][0] = 0ull; acc[i][1] = 0ull; }

        #pragma unroll 7
        for (int j = 0; j < K_DIM; j++) {
            float4 a0 = *reinterpret_cast<const float4*>(aBase + j * AROW);
            float4 a1 = *reinterpret_cast<const float4*>(aBase + j * AROW + 4);
            ulonglong2 yv2 = *reinterpret_cast<const ulonglong2*>(yBase + j * C_TILE);
            u64 y0 = yv2.x, y1 = yv2.y;
            float av[RPT] = {a0.x, a0.y, a0.z, a0.w, a1.x, a1.y, a1.z};
            #pragma unroll
            for (int i = 0; i < RPT; i++) {
                u64 d = dupf(av[i]);
                fma2(acc[i][0], d, y0);
                fma2(acc[i][1], d, y1);
            }
        }
        __syncthreads();

        float t_new = 0.5f * (1.0f + sqrtf(fmaf(4.0f * t_old, t_old, 1.0f)));
        float mu = (t_old - 1.0f) / t_new;
        t_old = t_new;

        if (active) {
            #pragma unroll
            for (int i = 0; i < RPT; i++) {
                int base = (k0 + i) * C_TILE + (p << 2);
                float2 q0 = unpk(acc[i][0]);
                float2 q1 = unpk(acc[i][1]);
                float4 c4 = *reinterpret_cast<const float4*>(sC + base);
                float w0, w1, w2, w3;
                if (PHASE == 2) {
                    float4 w4 = *reinterpret_cast<const float4*>(sW + base);
                    w0 = w4.x; w1 = w4.y; w2 = w4.z; w3 = w4.w;
                } else { w0 = w1 = w2 = w3 = lamLinv; }
                float v0 = q0.x + c4.x, v1 = q0.y + c4.y;
                float v2 = q1.x + c4.z, v3 = q1.y + c4.w;
                float x0 = fmaxf(v0 - w0, 0.f) + fminf(v0 + w0, 0.f);
                float x1 = fmaxf(v1 - w1, 0.f) + fminf(v1 + w1, 0.f);
                float x2 = fmaxf(v2 - w2, 0.f) + fminf(v2 + w2, 0.f);
                float x3 = fmaxf(v3 - w3, 0.f) + fminf(v3 + w3, 0.f);
                float4 yv;
                yv.x = fmaf(mu, x0 - xo[i][0], x0);
                yv.y = fmaf(mu, x1 - xo[i][1], x1);
                yv.z = fmaf(mu, x2 - xo[i][2], x2);
                yv.w = fmaf(mu, x3 - xo[i][3], x3);
                xo[i][0] = x0; xo[i][1] = x1; xo[i][2] = x2; xo[i][3] = x3;
                *reinterpret_cast<float4*>(sY + base) = yv;
            }
        }
        __syncthreads();
    }

    if (active) {
        float* xout = (PHASE == 1) ? g_x1 : code_out;
        #pragma unroll
        for (int i = 0; i < RPT; i++) {
            int k = k0 + i;
            #pragma unroll
            for (int c = 0; c < 4; c++) {
                int col = col0 + (p << 2) + c;
                if (col < NCOLS) {
                    int n = col / F_DIM, f = col - n * F_DIM;
                    xout[(n * K_DIM + k) * F_DIM + f] = xo[i][c];
                }
            }
        }
    }
}

// ---------------- sum of wn^2 over phase-1 code ----------------
__global__ void wn2_kernel() {
    __shared__ double red[256];
    double local = 0.0;
    long stride = (long)gridDim.x * blockDim.x;
    for (long i = (long)blockIdx.x * blockDim.x + threadIdx.x; i < NKF; i += stride) {
        float w = 1.0f / (fabsf(g_x1[i]) + 0.01f);
        local += (double)w * (double)w;
    }
    red[threadIdx.x] = local;
    __syncthreads();
    for (int o = 128; o > 0; o >>= 1) { if (threadIdx.x < o) red[threadIdx.x] += red[threadIdx.x + o]; __syncthreads(); }
    if (threadIdx.x == 0) atomicAdd(&g_wn2, red[0]);
}

__global__ void scale_kernel() {
    float nrm = (float)sqrt(g_wn2);
    g_scal[2] = g_scal[1] * (float)K_DIM / nrm;   // wl = wscale / (|x1|+0.01)
}

// ---------------- reconst = D @ code, plus copy D to output ----------------
__global__ void reconst_kernel(const float* __restrict__ code,
                               float* __restrict__ outD, float* __restrict__ outR) {
    extern __shared__ float sm[];
    float* sc = sm;                     // 161*50
    float* sd = sm + K_DIM * F_DIM;     // 36*161
    int n = blockIdx.x, tid = threadIdx.x;
    for (int i = tid; i < K_DIM * F_DIM; i += blockDim.x) sc[i] = code[n * K_DIM * F_DIM + i];
    for (int i = tid; i < T_LEN * K_DIM; i += blockDim.x) sd[i] = g_D[i];
    __syncthreads();
    for (int o = tid; o < T_LEN * F_DIM; o += blockDim.x) {
        int t = o / F_DIM, f = o - t * F_DIM;
        float s = 0.f;
        for (int k = 0; k < K_DIM; k++) s = fmaf(sd[t * K_DIM + k], sc[k * F_DIM + f], s);
        outR[n * T_LEN * F_DIM + o] = s;
    }
    if (n == 0) for (int i = tid; i < T_LEN * K_DIM; i += blockDim.x) outD[i] = g_D[i];
}

// ---------------- launch ----------------
extern "C" void kernel_launch(void* const* d_in, const int* in_sizes, int n_in,
                              void* d_out, int out_size) {
    const float* x = nullptr; const float* rr = nullptr; const float* th = nullptr;
    for (int i = 0; i < n_in; i++) {
        if (in_sizes[i] == N_SAMP * T_LEN * F_DIM) x = (const float*)d_in[i];
        else if (in_sizes[i] == NPOLE) { if (!rr) rr = (const float*)d_in[i]; else th = (const float*)d_in[i]; }
    }
    // positional fallback (setup_inputs order: x, rr, theta, T)
    if (!x  && n_in > 0) x  = (const float*)d_in[0];
    if (!rr && n_in > 1) rr = (const float*)d_in[1];
    if (!th && n_in > 2) th = (const float*)d_in[2];

    float* out      = (float*)d_out;
    float* out_code = out;
    float* out_D    = out + NKF;
    float* out_R    = out_D + T_LEN * K_DIM;

    cudaFuncSetAttribute(fista_kernel<1>, cudaFuncAttributeMaxDynamicSharedMemorySize, SMEM_FISTA);
    cudaFuncSetAttribute(fista_kernel<2>, cudaFuncAttributeMaxDynamicSharedMemorySize, SMEM_FISTA);
    cudaFuncSetAttribute(reconst_kernel,  cudaFuncAttributeMaxDynamicSharedMemorySize,
                         (K_DIM * F_DIM + T_LEN * K_DIM) * (int)sizeof(float));

    setup_kernel<<<1, 256>>>(rr, th);
    dty_kernel<<<N_SAMP, 256>>>(x);
    fista_kernel<1><<<NTILES, NTHREADS, SMEM_FISTA>>>(out_code);
    wn2_kernel<<<148, 256>>>();
    scale_kernel<<<1, 1>>>();
    fista_kernel<2><<<NTILES, NTHREADS, SMEM_FISTA>>>(out_code);
    reconst_kernel<<<N_SAMP, 256, (K_DIM * F_DIM + T_LEN * K_DIM) * sizeof(float)>>>(out_code, out_D, out_R);
}

// round 3
// speedup vs baseline: 1.4361x; 1.4361x over previous
#include <cuda_runtime.h>
#include <math.h>

typedef unsigned long long u64;

#define N_SAMP 256
#define T_LEN  36
#define NPOLE  80
#define F_DIM  50
#define K_DIM  161                    // 1 + 2*80
#define NCOLS  (N_SAMP * F_DIM)      // 12800
#define NKF    (N_SAMP * K_DIM * F_DIM)  // 2,060,800
#define LAM    0.1f
#define ITERS  100

#define C_TILE 48          // columns per block-tile
#define PG     12          // col-groups of 4
#define NTHREADS 256
#define NTILES   267       // ceil(12800/48)

#define KPAD   168         // K padded to 21*8
#define KG_N   21          // k-groups of 8 (phase B)
#define TT_N   18          // t-pairs (phase A)

// smem layout (floats/u64 mixed; measured in bytes)
#define SZ_D2A (K_DIM * T_LEN * 8)      // 46368 : [k][t] dup'd D, u64
#define SZ_D2B (T_LEN * KPAD * 8)       // 48384 : [t][k] dup'd -D/L, u64
#define SZ_U   (T_LEN * C_TILE * 4)     //  6912 : u[t][col]
#define SZ_Y   (KPAD * C_TILE * 4)      // 32256 : y[k][col]
#define SZ_C   (KPAD * C_TILE * 4)      // 32256 : cminus / cplus
#define SMEM_FISTA (SZ_D2A + SZ_D2B + SZ_U + SZ_Y + 2 * SZ_C)   // 198,432 B

// ---------------- device scratch ----------------
__device__ float  g_D[T_LEN * K_DIM];
__device__ float  g_c0[NKF];
__device__ float  g_x1[NKF];
__device__ float  g_scal[4];   // 0: Linv, 1: lam/L, 2: wscale
__device__ double g_wn2;

// ---------------- f32x2 helpers ----------------
__device__ __forceinline__ u64 dupf(float a) {
    u64 r; asm("mov.b64 %0, {%1, %1};" : "=l"(r) : "f"(a)); return r;
}
__device__ __forceinline__ void fma2(u64 &d, u64 a, u64 b) {
    asm("fma.rn.f32x2 %0, %1, %2, %3;" : "=l"(d) : "l"(a), "l"(b), "l"(d));
}
__device__ __forceinline__ float2 unpk(u64 v) {
    float2 r; asm("mov.b64 {%0, %1}, %2;" : "=f"(r.x), "=f"(r.y) : "l"(v)); return r;
}

// ---------------- setup: build D, compute L = ||DtD||_F ----------------
__global__ void setup_kernel(const float* __restrict__ rr, const float* __restrict__ theta) {
    int tid = threadIdx.x;
    for (int idx = tid; idx < T_LEN * K_DIM; idx += blockDim.x) {
        int t = idx / K_DIM, k = idx - (idx / K_DIM) * K_DIM;
        float v;
        if (k == 0) v = 1.0f;
        else if (k <= NPOLE) {
            int p = k - 1;
            v = powf(rr[p], (float)t) * cosf((float)t * theta[p]);
        } else {
            int p = k - 1 - NPOLE;
            v = powf(rr[p], (float)t) * sinf((float)t * theta[p]);
        }
        g_D[idx] = v;
    }
    if (tid == 0) g_wn2 = 0.0;
    __syncthreads();

    __shared__ double red[256];
    double local = 0.0;
    for (int idx = tid; idx < K_DIM * K_DIM; idx += blockDim.x) {
        int a = idx / K_DIM, b = idx - a * K_DIM;
        float s = 0.f;
        for (int t = 0; t < T_LEN; t++) s = fmaf(g_D[t * K_DIM + a], g_D[t * K_DIM + b], s);
        local += (double)s * (double)s;
    }
    red[tid] = local;
    __syncthreads();
    for (int o = 128; o > 0; o >>= 1) { if (tid < o) red[tid] += red[tid + o]; __syncthreads(); }
    if (tid == 0) {
        float L = (float)sqrt(red[0]);       // Frobenius norm of DtD
        g_scal[0] = 1.0f / L;
        g_scal[1] = LAM / L;
    }
}

// ---------------- c0 = (D^T Y) / L ----------------
__global__ void dty_kernel(const float* __restrict__ x) {
    __shared__ float xs[T_LEN * F_DIM];
    __shared__ float Ds[T_LEN * K_DIM];
    int n = blockIdx.x, tid = threadIdx.x;
    for (int i = tid; i < T_LEN * F_DIM; i += blockDim.x) xs[i] = x[n * T_LEN * F_DIM + i];
    for (int i = tid; i < T_LEN * K_DIM; i += blockDim.x) Ds[i] = g_D[i];
    __syncthreads();
    float Linv = g_scal[0];
    for (int o = tid; o < K_DIM * F_DIM; o += blockDim.x) {
        int k = o / F_DIM, f = o - k * F_DIM;
        float s = 0.f;
        for (int t = 0; t < T_LEN; t++) s = fmaf(Ds[t * K_DIM + k], xs[t * F_DIM + f], s);
        g_c0[n * K_DIM * F_DIM + o] = s * Linv;
    }
}

// ---------------- FISTA via rank-36 factorization: A y = y - D^T(D y)/L ----------------
template <int PHASE>
__global__ __launch_bounds__(NTHREADS, 1)
void fista_kernel(float* __restrict__ code_out) {
    extern __shared__ char smem[];
    u64*   sDA = (u64*)(smem);                       // [k][t]  dup(D[t][k])
    u64*   sDB = (u64*)(smem + SZ_D2A);              // [t][k]  dup(-D[t][k]/L), k padded
    float* sU  = (float*)(smem + SZ_D2A + SZ_D2B);   // [t][col]
    float* sY  = sU + T_LEN * C_TILE;                // [k][col], k padded
    float* sCm = sY + KPAD * C_TILE;
    float* sCp = sCm + KPAD * C_TILE;

    const int tid = threadIdx.x;
    const float Linv    = g_scal[0];
    const float lamLinv = g_scal[1];
    const float wscale  = g_scal[2];

    // ---- stage D in both duplicated layouts ----
    for (int idx = tid; idx < T_LEN * K_DIM; idx += NTHREADS) {
        int t = idx / K_DIM, k = idx - (idx / K_DIM) * K_DIM;
        float d = g_D[idx];
        sDA[k * T_LEN + t] = dupf(d);
        sDB[t * KPAD + k]  = dupf(-d * Linv);
    }
    for (int idx = tid; idx < T_LEN * (KPAD - K_DIM); idx += NTHREADS) {
        int t = idx / (KPAD - K_DIM), k = K_DIM + idx % (KPAD - K_DIM);
        sDB[t * KPAD + k] = 0ull;
    }

    // ---- stage cminus / cplus and zero y ----
    const int col0 = blockIdx.x * C_TILE;
    for (int i = tid; i < KPAD * C_TILE; i += NTHREADS) {
        int k = i / C_TILE, c = i - (i / C_TILE) * C_TILE;
        float cm = 0.f, cp = 0.f;
        if (k < K_DIM) {
            int col = col0 + c; if (col >= NCOLS) col = NCOLS - 1;
            int n = col / F_DIM, f = col - n * F_DIM;
            int g = (n * K_DIM + k) * F_DIM + f;
            float c0 = g_c0[g];
            float w  = (PHASE == 2) ? (wscale / (fabsf(g_x1[g]) + 0.01f)) : lamLinv;
            cm = c0 - w; cp = c0 + w;
        }
        sCm[i] = cm; sCp[i] = cp;
        sY[i] = 0.0f;
    }
    __syncthreads();

    // ---- thread roles ----
    const bool actA = tid < TT_N * PG;           // 216
    const int  ttA  = tid / PG;                  // t-pair 0..17
    const int  pA   = tid - ttA * PG;            // col-group 0..11
    const bool actB = tid < KG_N * PG;           // 252
    const int  kgB  = tid / PG;                  // k-group 0..20
    const int  pB   = tid - kgB * PG;
    const int  k0   = kgB * 8;

    float xo[8][4];
    #pragma unroll
    for (int i = 0; i < 8; i++) { xo[i][0] = xo[i][1] = xo[i][2] = xo[i][3] = 0.f; }
    float t_old = 1.0f;

    const u64*   aDA = sDA + 2 * ttA;            // [k][t0..t0+1]
    const float* yA  = sY + 4 * pA;
    const u64*   bDB = sDB + k0;                 // [t][k0..k0+7]
    const float* uB  = sU + 4 * pB;

    for (int it = 0; it < ITERS; it++) {
        // ======== phase A: u[t][c] = sum_k D[t][k] * y[k][c] ========
        if (actA) {
            u64 a00 = 0, a01 = 0, a10 = 0, a11 = 0;  // (t0,c01)(t0,c23)(t1,c01)(t1,c23)
            #pragma unroll 7
            for (int k = 0; k < K_DIM; k++) {
                ulonglong2 yv = *reinterpret_cast<const ulonglong2*>(yA + k * C_TILE);
                ulonglong2 dv = *reinterpret_cast<const ulonglong2*>(aDA + k * T_LEN);
                fma2(a00, dv.x, yv.x); fma2(a01, dv.x, yv.y);
                fma2(a10, dv.y, yv.x); fma2(a11, dv.y, yv.y);
            }
            int t0 = 2 * ttA;
            float2 q0 = unpk(a00), q1 = unpk(a01), q2 = unpk(a10), q3 = unpk(a11);
            float4 r0 = make_float4(q0.x, q0.y, q1.x, q1.y);
            float4 r1 = make_float4(q2.x, q2.y, q3.x, q3.y);
            *reinterpret_cast<float4*>(sU + t0 * C_TILE + 4 * pA) = r0;
            *reinterpret_cast<float4*>(sU + (t0 + 1) * C_TILE + 4 * pA) = r1;
        }
        __syncthreads();

        // ======== phase B: v = -D^T u / L ; shrink + momentum ========
        float t_new = 0.5f * (1.0f + sqrtf(fmaf(4.0f * t_old, t_old, 1.0f)));
        float mu = (t_old - 1.0f) / t_new;
        t_old = t_new;

        if (actB) {
            u64 acc[8][2];
            #pragma unroll
            for (int i = 0; i < 8; i++) { acc[i][0] = 0ull; acc[i][1] = 0ull; }

            #pragma unroll 4
            for (int t = 0; t < T_LEN; t++) {
                ulonglong2 uv = *reinterpret_cast<const ulonglong2*>(uB + t * C_TILE);
                const u64* drow = bDB + t * KPAD;
                ulonglong2 d01 = *reinterpret_cast<const ulonglong2*>(drow);
                ulonglong2 d23 = *reinterpret_cast<const ulonglong2*>(drow + 2);
                ulonglong2 d45 = *reinterpret_cast<const ulonglong2*>(drow + 4);
                ulonglong2 d67 = *reinterpret_cast<const ulonglong2*>(drow + 6);
                fma2(acc[0][0], d01.x, uv.x); fma2(acc[0][1], d01.x, uv.y);
                fma2(acc[1][0], d01.y, uv.x); fma2(acc[1][1], d01.y, uv.y);
                fma2(acc[2][0], d23.x, uv.x); fma2(acc[2][1], d23.x, uv.y);
                fma2(acc[3][0], d23.y, uv.x); fma2(acc[3][1], d23.y, uv.y);
                fma2(acc[4][0], d45.x, uv.x); fma2(acc[4][1], d45.x, uv.y);
                fma2(acc[5][0], d45.y, uv.x); fma2(acc[5][1], d45.y, uv.y);
                fma2(acc[6][0], d67.x, uv.x); fma2(acc[6][1], d67.x, uv.y);
                fma2(acc[7][0], d67.y, uv.x); fma2(acc[7][1], d67.y, uv.y);
            }

            #pragma unroll
            for (int i = 0; i < 8; i++) {
                int base = (k0 + i) * C_TILE + 4 * pB;
                float4 y4 = *reinterpret_cast<const float4*>(sY + base);
                float4 cm = *reinterpret_cast<const float4*>(sCm + base);
                float4 cp = *reinterpret_cast<const float4*>(sCp + base);
                float2 q0 = unpk(acc[i][0]);
                float2 q1 = unpk(acc[i][1]);
                float v0 = y4.x + q0.x, v1 = y4.y + q0.y;
                float v2 = y4.z + q1.x, v3 = y4.w + q1.y;
                float x0 = fmaxf(v0 + cm.x, 0.f) + fminf(v0 + cp.x, 0.f);
                float x1 = fmaxf(v1 + cm.y, 0.f) + fminf(v1 + cp.y, 0.f);
                float x2 = fmaxf(v2 + cm.z, 0.f) + fminf(v2 + cp.z, 0.f);
                float x3 = fmaxf(v3 + cm.w, 0.f) + fminf(v3 + cp.w, 0.f);
                float4 yv;
                yv.x = fmaf(mu, x0 - xo[i][0], x0);
                yv.y = fmaf(mu, x1 - xo[i][1], x1);
                yv.z = fmaf(mu, x2 - xo[i][2], x2);
                yv.w = fmaf(mu, x3 - xo[i][3], x3);
                xo[i][0] = x0; xo[i][1] = x1; xo[i][2] = x2; xo[i][3] = x3;
                *reinterpret_cast<float4*>(sY + base) = yv;
            }
        }
        __syncthreads();
    }

    // ---- write out x ----
    if (actB) {
        float* xout = (PHASE == 1) ? g_x1 : code_out;
        #pragma unroll
        for (int i = 0; i < 8; i++) {
            int k = k0 + i;
            if (k < K_DIM) {
                #pragma unroll
                for (int c = 0; c < 4; c++) {
                    int col = col0 + 4 * pB + c;
                    if (col < NCOLS) {
                        int n = col / F_DIM, f = col - n * F_DIM;
                        xout[(n * K_DIM + k) * F_DIM + f] = xo[i][c];
                    }
                }
            }
        }
    }
}

// ---------------- sum of wn^2 over phase-1 code ----------------
__global__ void wn2_kernel() {
    __shared__ double red[256];
    double local = 0.0;
    long stride = (long)gridDim.x * blockDim.x;
    for (long i = (long)blockIdx.x * blockDim.x + threadIdx.x; i < NKF; i += stride) {
        float w = 1.0f / (fabsf(g_x1[i]) + 0.01f);
        local += (double)w * (double)w;
    }
    red[threadIdx.x] = local;
    __syncthreads();
    for (int o = 128; o > 0; o >>= 1) { if (threadIdx.x < o) red[threadIdx.x] += red[threadIdx.x + o]; __syncthreads(); }
    if (threadIdx.x == 0) atomicAdd(&g_wn2, red[0]);
}

__global__ void scale_kernel() {
    float nrm = (float)sqrt(g_wn2);
    g_scal[2] = g_scal[1] * (float)K_DIM / nrm;   // w = wscale / (|x1|+0.01)
}

// ---------------- reconst = D @ code, plus copy D to output ----------------
__global__ void reconst_kernel(const float* __restrict__ code,
                               float* __restrict__ outD, float* __restrict__ outR) {
    extern __shared__ float sm[];
    float* sc = sm;                     // 161*50
    float* sd = sm + K_DIM * F_DIM;     // 36*161
    int n = blockIdx.x, tid = threadIdx.x;
    for (int i = tid; i < K_DIM * F_DIM; i += blockDim.x) sc[i] = code[n * K_DIM * F_DIM + i];
    for (int i = tid; i < T_LEN * K_DIM; i += blockDim.x) sd[i] = g_D[i];
    __syncthreads();
    for (int o = tid; o < T_LEN * F_DIM; o += blockDim.x) {
        int t = o / F_DIM, f = o - t * F_DIM;
        float s = 0.f;
        for (int k = 0; k < K_DIM; k++) s = fmaf(sd[t * K_DIM + k], sc[k * F_DIM + f], s);
        outR[n * T_LEN * F_DIM + o] = s;
    }
    if (n == 0) for (int i = tid; i < T_LEN * K_DIM; i += blockDim.x) outD[i] = g_D[i];
}

// ---------------- launch ----------------
extern "C" void kernel_launch(void* const* d_in, const int* in_sizes, int n_in,
                              void* d_out, int out_size) {
    const float* x = nullptr; const float* rr = nullptr; const float* th = nullptr;
    for (int i = 0; i < n_in; i++) {
        if (in_sizes[i] == N_SAMP * T_LEN * F_DIM) x = (const float*)d_in[i];
        else if (in_sizes[i] == NPOLE) { if (!rr) rr = (const float*)d_in[i]; else th = (const float*)d_in[i]; }
    }
    if (!x  && n_in > 0) x  = (const float*)d_in[0];
    if (!rr && n_in > 1) rr = (const float*)d_in[1];
    if (!th && n_in > 2) th = (const float*)d_in[2];

    float* out      = (float*)d_out;
    float* out_code = out;
    float* out_D    = out + NKF;
    float* out_R    = out_D + T_LEN * K_DIM;

    cudaFuncSetAttribute(fista_kernel<1>, cudaFuncAttributeMaxDynamicSharedMemorySize, SMEM_FISTA);
    cudaFuncSetAttribute(fista_kernel<2>, cudaFuncAttributeMaxDynamicSharedMemorySize, SMEM_FISTA);
    cudaFuncSetAttribute(reconst_kernel,  cudaFuncAttributeMaxDynamicSharedMemorySize,
                         (K_DIM * F_DIM + T_LEN * K_DIM) * (int)sizeof(float));

    setup_kernel<<<1, 256>>>(rr, th);
    dty_kernel<<<N_SAMP, 256>>>(x);
    fista_kernel<1><<<NTILES, NTHREADS, SMEM_FISTA>>>(out_code);
    wn2_kernel<<<148, 256>>>();
    scale_kernel<<<1, 1>>>();
    fista_kernel<2><<<NTILES, NTHREADS, SMEM_FISTA>>>(out_code);
    reconst_kernel<<<N_SAMP, 256, (K_DIM * F_DIM + T_LEN * K_DIM) * sizeof(float)>>>(out_code, out_D, out_R);
}